// round 10
// baseline (speedup 1.0000x reference)
#include <cuda_runtime.h>
#include <cstdint>

// Fixed shape: stimuli [4,32,304,608,1] fp32, eye [4,32,2,3]
constexpr int H  = 304;
constexpr int W  = 608;
constexpr int HW = H * W;
constexpr int NFRAMES = 128;

// Warp output tile: 8 cols x 4 rows per iteration, 4 iterations (8x16 px).
constexpr int TCOLS = 8;
constexpr int TROWS = 4;
constexpr int ITERS = 4;
constexpr int COL_TILES = W / TCOLS;               // 76
constexpr int ROW_TILES = H / (TROWS * ITERS);     // 19
constexpr int WARPS_PER_FRAME = COL_TILES * ROW_TILES;  // 1444
constexpr int WARPS_PER_BLOCK = 4;                 // 128 threads
constexpr int BLOCKS_X = WARPS_PER_FRAME / WARPS_PER_BLOCK;  // 361

struct Group {
    float x, y;          // source coords
    float x0f, x1f, y0f, y1f;
    float Ia, Ib, Ic, Id;
};

__global__ __launch_bounds__(128, 10) void warp_bilinear_kernel(
    const float* __restrict__ stimuli,
    const float* __restrict__ eye,
    float* __restrict__ out)
{
    const int n    = blockIdx.y;
    const int warp = blockIdx.x * WARPS_PER_BLOCK + (threadIdx.x >> 5);
    const int lane = threadIdx.x & 31;

    const int rt = warp / COL_TILES;
    const int ct = warp - rt * COL_TILES;

    const int col   = ct * TCOLS + (lane & (TCOLS - 1));
    const int rbase = rt * (TROWS * ITERS) + (lane >> 3);

    const float* a = eye + (size_t)n * 6;
    const float a00 = __ldg(a + 0);
    const float a01 = __ldg(a + 1);
    const float a02 = __ldg(a + 2);
    const float a10 = __ldg(a + 3);
    const float a11 = __ldg(a + 4);
    const float a12 = __ldg(a + 5);

    // jnp.linspace(-1,1,n): v[i] = fl(-1 + fl(i*step)), endpoint exactly 1.0
    const float step_x = 2.0f / (float)(W - 1);
    const float step_y = 2.0f / (float)(H - 1);
    const float xt = (col == W - 1) ? 1.0f
                   : __fadd_rn(-1.0f, __fmul_rn((float)col, step_x));

    const float a00xt = __fmul_rn(a00, xt);
    const float a10xt = __fmul_rn(a10, xt);

    const float* __restrict__ img = stimuli + (size_t)n * HW;
    float* __restrict__       dst = out     + (size_t)n * HW;

    // Issue coords + 4 gathers for iteration i
    auto load_group = [&](int i) -> Group {
        Group g;
        const int row = rbase + i * TROWS;
        const float yt = (row == H - 1) ? 1.0f
                       : __fadd_rn(-1.0f, __fmul_rn((float)row, step_y));

        const float Tx = __fadd_rn(__fmaf_rn(a01, yt, a00xt), a02);
        const float Ty = __fadd_rn(__fmaf_rn(a11, yt, a10xt), a12);
        g.x = __fmul_rn(__fadd_rn(Tx, 1.0f), (float)W * 0.5f);
        g.y = __fmul_rn(__fadd_rn(Ty, 1.0f), (float)H * 0.5f);

        // float-domain clamps; floor values integer-exact -> bitwise equal
        // to the reference's int clamp + cast
        const float fx0 = floorf(g.x);
        const float fy0 = floorf(g.y);
        g.x0f = fminf(fmaxf(fx0, 0.0f), (float)(W - 1));
        g.x1f = fminf(fmaxf(__fadd_rn(fx0, 1.0f), 0.0f), (float)(W - 1));
        g.y0f = fminf(fmaxf(fy0, 0.0f), (float)(H - 1));
        g.y1f = fminf(fmaxf(__fadd_rn(fy0, 1.0f), 0.0f), (float)(H - 1));

        const int x0 = (int)g.x0f;
        const int x1 = (int)g.x1f;
        const int y0 = (int)g.y0f;
        const int y1 = (int)g.y1f;

        const int dx  = x1 - x0;          // 0 or 1
        const int dyW = (y1 - y0) * W;    // 0 or W

        const float* pA = img + y0 * W + x0;
        g.Ia = __ldg(pA);
        g.Ic = __ldg(pA + dx);
        g.Ib = __ldg(pA + dyW);
        g.Id = __ldg(pA + dyW + dx);
        return g;
    };

    // Blend with the reference's exact FP sequence, store
    auto blend_store = [&](int i, const Group& g) {
        const int row = rbase + i * TROWS;
        const float dx1 = __fsub_rn(g.x1f, g.x);
        const float dx0 = __fsub_rn(g.x, g.x0f);
        const float dy1 = __fsub_rn(g.y1f, g.y);
        const float dy0 = __fsub_rn(g.y, g.y0f);

        const float wa = __fmul_rn(dx1, dy1);
        const float wb = __fmul_rn(dx1, dy0);
        const float wc = __fmul_rn(dx0, dy1);
        const float wd = __fmul_rn(dx0, dy0);

        const float p1 = __fmul_rn(wa, g.Ia);
        const float p2 = __fmul_rn(wb, g.Ib);
        const float p3 = __fmul_rn(wc, g.Ic);
        const float p4 = __fmul_rn(wd, g.Id);
        dst[row * W + col] = __fadd_rn(__fadd_rn(__fadd_rn(p1, p2), p3), p4);
    };

    // Depth-2 software pipeline: next group's loads in flight while blending
    Group cur = load_group(0);
#pragma unroll
    for (int i = 0; i < ITERS - 1; ++i) {
        Group nxt = load_group(i + 1);
        blend_store(i, cur);
        cur = nxt;
    }
    blend_store(ITERS - 1, cur);
}

extern "C" void kernel_launch(void* const* d_in, const int* in_sizes, int n_in,
                              void* d_out, int out_size)
{
    const float* stimuli = (const float*)d_in[0];
    const float* eye     = (const float*)d_in[1];
    float* out           = (float*)d_out;

    dim3 block(WARPS_PER_BLOCK * 32);
    dim3 grid(BLOCKS_X, NFRAMES);
    warp_bilinear_kernel<<<grid, block>>>(stimuli, eye, out);
}

// round 11
// speedup vs baseline: 1.0076x; 1.0076x over previous
#include <cuda_runtime.h>
#include <cstdint>

// Fixed shape: stimuli [4,32,304,608,1] fp32, eye [4,32,2,3]
constexpr int H  = 304;
constexpr int W  = 608;
constexpr int HW = H * W;
constexpr int NFRAMES = 128;

// Warp output tile: 8 cols x 4 rows per iteration, 4 iterations (8x16 px).
constexpr int TCOLS = 8;
constexpr int TROWS = 4;
constexpr int ITERS = 4;
constexpr int COL_TILES = W / TCOLS;               // 76
constexpr int ROW_TILES = H / (TROWS * ITERS);     // 19
constexpr int WARPS_PER_FRAME = COL_TILES * ROW_TILES;  // 1444
constexpr int WARPS_PER_BLOCK = 4;                 // 128 threads
constexpr int BLOCKS_X = WARPS_PER_FRAME / WARPS_PER_BLOCK;  // 361

struct Px {
    float x, y;
    float x0f, x1f, y0f, y1f;
    float Ia, Ib, Ic, Id;
};

__global__ __launch_bounds__(128) void warp_bilinear_kernel(
    const float* __restrict__ stimuli,
    const float* __restrict__ eye,
    float* __restrict__ out)
{
    const int n    = blockIdx.y;
    const int warp = blockIdx.x * WARPS_PER_BLOCK + (threadIdx.x >> 5);
    const int lane = threadIdx.x & 31;

    const int rt = warp / COL_TILES;
    const int ct = warp - rt * COL_TILES;

    const int col   = ct * TCOLS + (lane & (TCOLS - 1));
    const int rbase = rt * (TROWS * ITERS) + (lane >> 3);

    const float* a = eye + (size_t)n * 6;
    const float a00 = __ldg(a + 0);
    const float a01 = __ldg(a + 1);
    const float a02 = __ldg(a + 2);
    const float a10 = __ldg(a + 3);
    const float a11 = __ldg(a + 4);
    const float a12 = __ldg(a + 5);

    // jnp.linspace(-1,1,n): v[i] = fl(-1 + fl(i*step)), endpoint exactly 1.0
    const float step_x = 2.0f / (float)(W - 1);
    const float step_y = 2.0f / (float)(H - 1);
    const float xt = (col == W - 1) ? 1.0f
                   : __fadd_rn(-1.0f, __fmul_rn((float)col, step_x));

    const float a00xt = __fmul_rn(a00, xt);
    const float a10xt = __fmul_rn(a10, xt);

    const float* __restrict__ img = stimuli + (size_t)n * HW;
    float* __restrict__       dst = out     + (size_t)n * HW;

    auto load_px = [&](int i) -> Px {
        Px g;
        const int row = rbase + i * TROWS;
        const float yt = (row == H - 1) ? 1.0f
                       : __fadd_rn(-1.0f, __fmul_rn((float)row, step_y));

        const float Tx = __fadd_rn(__fmaf_rn(a01, yt, a00xt), a02);
        const float Ty = __fadd_rn(__fmaf_rn(a11, yt, a10xt), a12);
        g.x = __fmul_rn(__fadd_rn(Tx, 1.0f), (float)W * 0.5f);
        g.y = __fmul_rn(__fadd_rn(Ty, 1.0f), (float)H * 0.5f);

        // float-domain clamps; floor values are integer-exact -> bitwise equal
        // to the reference's int clamp + cast (validated R9)
        const float fx0 = floorf(g.x);
        const float fy0 = floorf(g.y);
        g.x0f = fminf(fmaxf(fx0, 0.0f), (float)(W - 1));
        g.x1f = fminf(fmaxf(__fadd_rn(fx0, 1.0f), 0.0f), (float)(W - 1));
        g.y0f = fminf(fmaxf(fy0, 0.0f), (float)(H - 1));
        g.y1f = fminf(fmaxf(__fadd_rn(fy0, 1.0f), 0.0f), (float)(H - 1));

        // Fused float linear offsets (integer-exact: <= 184831 < 2^24)
        const float offAf = __fmaf_rn(g.y0f, (float)W, g.x0f);
        const float offBf = __fmaf_rn(g.y1f, (float)W, g.x0f);
        const int offA = (int)offAf;
        const int offB = (int)offBf;
        const int dx   = (int)__fsub_rn(g.x1f, g.x0f);   // 0 or 1

        g.Ia = __ldg(img + offA);
        g.Ic = __ldg(img + offA + dx);
        g.Ib = __ldg(img + offB);
        g.Id = __ldg(img + offB + dx);
        return g;
    };

    auto blend_store = [&](int i, const Px& g) {
        const int row = rbase + i * TROWS;
        const float dx1 = __fsub_rn(g.x1f, g.x);
        const float dx0 = __fsub_rn(g.x, g.x0f);
        const float dy1 = __fsub_rn(g.y1f, g.y);
        const float dy0 = __fsub_rn(g.y, g.y0f);

        const float wa = __fmul_rn(dx1, dy1);
        const float wb = __fmul_rn(dx1, dy0);
        const float wc = __fmul_rn(dx0, dy1);
        const float wd = __fmul_rn(dx0, dy0);

        const float p1 = __fmul_rn(wa, g.Ia);
        const float p2 = __fmul_rn(wb, g.Ib);
        const float p3 = __fmul_rn(wc, g.Ic);
        const float p4 = __fmul_rn(wd, g.Id);
        dst[row * W + col] = __fadd_rn(__fadd_rn(__fadd_rn(p1, p2), p3), p4);
    };

    // Pairwise batching: 8 loads in flight, then 2 blends. Fits ~40 regs.
#pragma unroll
    for (int i = 0; i < ITERS; i += 2) {
        Px g0 = load_px(i);
        Px g1 = load_px(i + 1);
        blend_store(i, g0);
        blend_store(i + 1, g1);
    }
}

extern "C" void kernel_launch(void* const* d_in, const int* in_sizes, int n_in,
                              void* d_out, int out_size)
{
    const float* stimuli = (const float*)d_in[0];
    const float* eye     = (const float*)d_in[1];
    float* out           = (float*)d_out;

    dim3 block(WARPS_PER_BLOCK * 32);
    dim3 grid(BLOCKS_X, NFRAMES);
    warp_bilinear_kernel<<<grid, block>>>(stimuli, eye, out);
}

// round 12
// speedup vs baseline: 1.0288x; 1.0211x over previous
#include <cuda_runtime.h>
#include <cstdint>

// Fixed shape: stimuli [4,32,304,608,1] fp32, eye [4,32,2,3]
constexpr int H  = 304;
constexpr int W  = 608;
constexpr int HW = H * W;
constexpr int NFRAMES = 128;

// Warp output tile: 8 cols x 4 rows per iteration, 4 iterations (8x16 px).
// Analytically optimal: minimizes distinct source lines per gather LDG.
constexpr int TCOLS = 8;
constexpr int TROWS = 4;
constexpr int ITERS = 4;
constexpr int COL_TILES = W / TCOLS;               // 76
constexpr int ROW_TILES = H / (TROWS * ITERS);     // 19
constexpr int WARPS_PER_FRAME = COL_TILES * ROW_TILES;  // 1444
constexpr int WARPS_PER_BLOCK = 4;                 // 128 threads
constexpr int BLOCKS_X = WARPS_PER_FRAME / WARPS_PER_BLOCK;  // 361

__global__ __launch_bounds__(WARPS_PER_BLOCK * 32) void warp_bilinear_kernel(
    const float* __restrict__ stimuli,
    const float* __restrict__ eye,
    float* __restrict__ out)
{
    const int n    = blockIdx.y;
    const int warp = blockIdx.x * WARPS_PER_BLOCK + (threadIdx.x >> 5);
    const int lane = threadIdx.x & 31;

    const int rt = warp / COL_TILES;                // row tile 0..18
    const int ct = warp - rt * COL_TILES;           // col tile 0..75

    const int col   = ct * TCOLS + (lane & (TCOLS - 1));
    const int rbase = rt * (TROWS * ITERS) + (lane >> 3);

    const float* a = eye + (size_t)n * 6;
    const float a00 = __ldg(a + 0);
    const float a01 = __ldg(a + 1);
    const float a02 = __ldg(a + 2);
    const float a10 = __ldg(a + 3);
    const float a11 = __ldg(a + 4);
    const float a12 = __ldg(a + 5);

    // jnp.linspace(-1,1,n): v[i] = fl(-1 + fl(i*step)), endpoint exactly 1.0
    const float step_x = 2.0f / (float)(W - 1);
    const float step_y = 2.0f / (float)(H - 1);
    const float xt = (col == W - 1) ? 1.0f
                   : __fadd_rn(-1.0f, __fmul_rn((float)col, step_x));

    const float a00xt = __fmul_rn(a00, xt);
    const float a10xt = __fmul_rn(a10, xt);

    const float* __restrict__ img = stimuli + (size_t)n * HW;
    float* __restrict__       dst = out     + (size_t)n * HW;

#pragma unroll
    for (int i = 0; i < ITERS; ++i) {
        const int row = rbase + i * TROWS;
        const float yt = (row == H - 1) ? 1.0f
                       : __fadd_rn(-1.0f, __fmul_rn((float)row, step_y));

        // einsum k-order fmuladd chain: T = fadd(fmaf(a1, yt, a0*xt), a2)
        const float Tx = __fadd_rn(__fmaf_rn(a01, yt, a00xt), a02);
        const float Ty = __fadd_rn(__fmaf_rn(a11, yt, a10xt), a12);

        const float x = __fmul_rn(__fadd_rn(Tx, 1.0f), (float)W * 0.5f);
        const float y = __fmul_rn(__fadd_rn(Ty, 1.0f), (float)H * 0.5f);

        const int x0u = (int)floorf(x);
        const int y0u = (int)floorf(y);
        const int x0 = min(max(x0u, 0), W - 1);
        const int x1 = min(max(x0u + 1, 0), W - 1);
        const int y0 = min(max(y0u, 0), H - 1);
        const int y1 = min(max(y0u + 1, 0), H - 1);

        // Single address chain + small offsets (dx in {0,1}, dyW in {0,W})
        const int dx  = x1 - x0;
        const int dyW = (y1 - y0) * W;
        const float* pA = img + y0 * W + x0;

        const float Ia = __ldg(pA);
        const float Ic = __ldg(pA + dx);
        const float Ib = __ldg(pA + dyW);
        const float Id = __ldg(pA + dyW + dx);

        const float x0f = (float)x0, x1f = (float)x1;
        const float y0f = (float)y0, y1f = (float)y1;

        // separately rounded subs/muls (no fma contraction) — matches JAX
        const float dx1 = __fsub_rn(x1f, x);
        const float dx0 = __fsub_rn(x, x0f);
        const float dy1 = __fsub_rn(y1f, y);
        const float dy0 = __fsub_rn(y, y0f);

        const float wa = __fmul_rn(dx1, dy1);
        const float wb = __fmul_rn(dx1, dy0);
        const float wc = __fmul_rn(dx0, dy1);
        const float wd = __fmul_rn(dx0, dy0);

        const float p1 = __fmul_rn(wa, Ia);
        const float p2 = __fmul_rn(wb, Ib);
        const float p3 = __fmul_rn(wc, Ic);
        const float p4 = __fmul_rn(wd, Id);
        dst[row * W + col] = __fadd_rn(__fadd_rn(__fadd_rn(p1, p2), p3), p4);
    }
}

extern "C" void kernel_launch(void* const* d_in, const int* in_sizes, int n_in,
                              void* d_out, int out_size)
{
    const float* stimuli = (const float*)d_in[0];
    const float* eye     = (const float*)d_in[1];
    float* out           = (float*)d_out;

    dim3 block(WARPS_PER_BLOCK * 32);
    dim3 grid(BLOCKS_X, NFRAMES);
    warp_bilinear_kernel<<<grid, block>>>(stimuli, eye, out);
}